// round 13
// baseline (speedup 1.0000x reference)
#include <cuda_runtime.h>

// ---------------------------------------------------------------------------
// 3-layer stacked LSTM (batch=1), T=4096, IN=64, H=1024, OUT=1, fp32.
//
// Recurrence sync: NO chip barrier. Each h value is published as a tagged
// 64-bit word (epoch<<32 | float bits) via st.relaxed.gpu. Consumers poll the
// data word itself until the tag matches — the data IS the flag, so the per-
// step chain is one L2 store + one L2 observe instead of store+fence+flag+
// observe+refetch.
//   k_gemm  : g_pre[t,4H] = A[t,K] @ W_ih.T + (b_ih + b_hh)
//   k_rec   : persistent 128-CTA recurrent loop, W_hh register-resident
//   k_final : out[0] = hs[T-1] . w_lin + b_lin
// ---------------------------------------------------------------------------

#define T_STEPS 4096
#define HID     1024
#define GATES   4096
#define NCTA    128

typedef unsigned long long ull;

// Static scratch (allocation-free). Tagged h buffers: (epoch<<32)|f32 bits.
__device__ float g_pre[(size_t)T_STEPS * GATES];   // 64 MB
__device__ ull   g_hTA[(size_t)T_STEPS * HID];     // 32 MB (layers 0, 2 out)
__device__ ull   g_hTB[(size_t)T_STEPS * HID];     // 32 MB (layer 1 out)

// ---- sm_103a packed-fp32 / memory helpers ---------------------------------

__device__ __forceinline__ void fma2(ull& d, ull a, ull b) {
    asm("fma.rn.f32x2 %0, %1, %2, %0;" : "+l"(d) : "l"(a), "l"(b));
}
__device__ __forceinline__ ull pack2(float x, float y) {
    ull r; asm("mov.b64 %0, {%1, %2};" : "=l"(r) : "f"(x), "f"(y)); return r;
}
__device__ __forceinline__ float2 unpack2(ull v) {
    float2 f; asm("mov.b64 {%0, %1}, %2;" : "=f"(f.x), "=f"(f.y) : "l"(v)); return f;
}
// GPU-scope relaxed atomics: guaranteed coherent (L2), no tearing at 8B.
__device__ __forceinline__ ull ld_rlx(const ull* p) {
    ull v; asm volatile("ld.relaxed.gpu.global.b64 %0, [%1];" : "=l"(v) : "l"(p)); return v;
}
__device__ __forceinline__ void st_rlx(ull* p, ull v) {
    asm volatile("st.relaxed.gpu.global.b64 [%0], %1;" :: "l"(p), "l"(v) : "memory");
}
__device__ __forceinline__ float fast_tanh(float x) {
    // tanh(x) = 1 - 2/(e^{2x}+1); exact at both saturations.
    return 1.f - __fdividef(2.f, __expf(2.f * x) + 1.f);
}

// ---- GEMM: g_pre[t, r] = sum_k A[t,k]*W[r,k] + b1[r] + b2[r] ---------------
// A: [T_STEPS, K] (K = 64 plain, or 1024 from a tagged h buffer).
// 64x64 tile, 256 threads, 4x4 micro-tile with f32x2 packing.

#define GT  64
#define GR  64
#define GKC 16

__global__ void __launch_bounds__(256) k_gemm(
    const float* __restrict__ Ain, int src_sel, int K,
    const float* __restrict__ W,
    const float* __restrict__ b1, const float* __restrict__ b2)
{
    float* C = g_pre;

    __shared__ float As[GKC][GT + 4];
    __shared__ float Ws[GKC][GR + 4];

    const int t0   = blockIdx.y * GT;
    const int r0   = blockIdx.x * GR;
    const int tx   = threadIdx.x & 15;
    const int ty   = threadIdx.x >> 4;
    const int lrow = threadIdx.x >> 2;
    const int lcol = (threadIdx.x & 3) * 4;

    const ull* hsrc = (src_sel == 1) ? g_hTA : g_hTB;

    ull acc[4][2];
#pragma unroll
    for (int i = 0; i < 4; ++i) { acc[i][0] = 0ull; acc[i][1] = 0ull; }

    for (int kk = 0; kk < K; kk += GKC) {
        float4 va;
        if (src_sel == 0) {
            va = *(const float4*)(Ain + (size_t)(t0 + lrow) * K + kk + lcol);
        } else {
            const ull* hp = hsrc + (size_t)(t0 + lrow) * K + kk + lcol;
            va.x = __uint_as_float((unsigned)hp[0]);
            va.y = __uint_as_float((unsigned)hp[1]);
            va.z = __uint_as_float((unsigned)hp[2]);
            va.w = __uint_as_float((unsigned)hp[3]);
        }
        float4 vw = *(const float4*)(W + (size_t)(r0 + lrow) * K + kk + lcol);
        As[lcol + 0][lrow] = va.x; As[lcol + 1][lrow] = va.y;
        As[lcol + 2][lrow] = va.z; As[lcol + 3][lrow] = va.w;
        Ws[lcol + 0][lrow] = vw.x; Ws[lcol + 1][lrow] = vw.y;
        Ws[lcol + 2][lrow] = vw.z; Ws[lcol + 3][lrow] = vw.w;
        __syncthreads();
#pragma unroll
        for (int k = 0; k < GKC; ++k) {
            float4 a = *(const float4*)&As[k][4 * ty];
            const ull* wp = (const ull*)&Ws[k][4 * tx];
            ull w0 = wp[0], w1 = wp[1];
            ull ap;
            ap = pack2(a.x, a.x); fma2(acc[0][0], ap, w0); fma2(acc[0][1], ap, w1);
            ap = pack2(a.y, a.y); fma2(acc[1][0], ap, w0); fma2(acc[1][1], ap, w1);
            ap = pack2(a.z, a.z); fma2(acc[2][0], ap, w0); fma2(acc[2][1], ap, w1);
            ap = pack2(a.w, a.w); fma2(acc[3][0], ap, w0); fma2(acc[3][1], ap, w1);
        }
        __syncthreads();
    }

    const int r = r0 + 4 * tx;
    float4 bias;
    bias.x = b1[r + 0] + b2[r + 0];
    bias.y = b1[r + 1] + b2[r + 1];
    bias.z = b1[r + 2] + b2[r + 2];
    bias.w = b1[r + 3] + b2[r + 3];
#pragma unroll
    for (int i = 0; i < 4; ++i) {
        float2 p0 = unpack2(acc[i][0]);
        float2 p1 = unpack2(acc[i][1]);
        float4 o;
        o.x = p0.x + bias.x; o.y = p0.y + bias.y;
        o.z = p1.x + bias.z; o.w = p1.y + bias.w;
        *(float4*)(C + (size_t)(t0 + 4 * ty + i) * GATES + r) = o;
    }
}

// ---- Persistent recurrent kernel -------------------------------------------
// 128 CTAs x 256 threads. Warp w of CTA b owns hidden unit b*8+w and its 4
// gate rows of W_hh; lane l keeps columns {64k+2l, 64k+2l+1} (k=0..15) in
// registers (64 ull). Per step:
//   each thread polls 4 tagged h(t-1) words until tag==epoch, strips tags,
//   stages to SMEM -> bar -> 16 LDS.64 feeding 64 fma2 per lane ->
//   4x xor-shfl reduce -> lane 0 gate math -> tagged st.relaxed of h(t).
// No chip barrier: tag-match on the data word is the only synchronization.

__global__ void __launch_bounds__(256, 1) k_rec(
    const float* __restrict__ whh, int out_sel, int layer)
{
    ull* hT = (out_sel == 0) ? g_hTA : g_hTB;
    const float* pre = g_pre;

    __shared__ __align__(16) float h_sm[HID];

    const int tid  = threadIdx.x;
    const int w    = tid >> 5;
    const int l    = tid & 31;
    const int unit = blockIdx.x * 8 + w;
    const unsigned ebase = (unsigned)(layer * T_STEPS);

    // Register-resident W_hh slice.
    ull wgt[4][16];
#pragma unroll
    for (int g = 0; g < 4; ++g) {
        const float* row = whh + (size_t)(g * HID + unit) * HID + 2 * l;
#pragma unroll
        for (int k = 0; k < 16; ++k)
            wgt[g][k] = *(const ull*)(row + 64 * k);
    }

    float c_state = 0.f;
    float p0 = 0.f, p1 = 0.f, p2 = 0.f, p3 = 0.f;
    if (l == 0) {
        p0 = pre[0 * HID + unit];
        p1 = pre[1 * HID + unit];
        p2 = pre[2 * HID + unit];
        p3 = pre[3 * HID + unit];
    }

    for (int t = 0; t < T_STEPS; ++t) {
        // Prefetch next step's pre (off the critical chain).
        float n0 = 0.f, n1 = 0.f, n2 = 0.f, n3 = 0.f;
        if (l == 0 && t + 1 < T_STEPS) {
            const float* pr = pre + (size_t)(t + 1) * GATES + unit;
            n0 = pr[0 * HID]; n1 = pr[1 * HID];
            n2 = pr[2 * HID]; n3 = pr[3 * HID];
        }

        if (t > 0) {
            // Poll 4 tagged words of h(t-1); tag must equal ebase + t.
            const ull* src = hT + (size_t)(t - 1) * HID + 4 * tid;
            const unsigned ep = ebase + (unsigned)t;
            ull v0 = ld_rlx(src + 0), v1 = ld_rlx(src + 1);
            ull v2 = ld_rlx(src + 2), v3 = ld_rlx(src + 3);
            while ((unsigned)(v0 >> 32) != ep) { __nanosleep(32); v0 = ld_rlx(src + 0); }
            while ((unsigned)(v1 >> 32) != ep) { v1 = ld_rlx(src + 1); }
            while ((unsigned)(v2 >> 32) != ep) { v2 = ld_rlx(src + 2); }
            while ((unsigned)(v3 >> 32) != ep) { v3 = ld_rlx(src + 3); }
            float4 f;
            f.x = __uint_as_float((unsigned)v0);
            f.y = __uint_as_float((unsigned)v1);
            f.z = __uint_as_float((unsigned)v2);
            f.w = __uint_as_float((unsigned)v3);
            *(float4*)&h_sm[4 * tid] = f;
        }
        __syncthreads();

        float d0 = 0.f, d1 = 0.f, d2 = 0.f, d3 = 0.f;
        if (t > 0) {
            const ull* hp = (const ull*)&h_sm[2 * l];
            ull a0 = 0ull, a1 = 0ull, a2 = 0ull, a3 = 0ull;
#pragma unroll
            for (int k = 0; k < 16; ++k) {
                ull hv = hp[32 * k];
                fma2(a0, wgt[0][k], hv);
                fma2(a1, wgt[1][k], hv);
                fma2(a2, wgt[2][k], hv);
                fma2(a3, wgt[3][k], hv);
            }
            float2 f0 = unpack2(a0), f1 = unpack2(a1);
            float2 f2 = unpack2(a2), f3 = unpack2(a3);
            d0 = f0.x + f0.y; d1 = f1.x + f1.y;
            d2 = f2.x + f2.y; d3 = f3.x + f3.y;
#pragma unroll
            for (int s = 16; s > 0; s >>= 1) {
                d0 += __shfl_xor_sync(0xffffffffu, d0, s);
                d1 += __shfl_xor_sync(0xffffffffu, d1, s);
                d2 += __shfl_xor_sync(0xffffffffu, d2, s);
                d3 += __shfl_xor_sync(0xffffffffu, d3, s);
            }
        }

        if (l == 0) {
            float gi = 1.f / (1.f + __expf(-(p0 + d0)));
            float gf = 1.f / (1.f + __expf(-(p1 + d1)));
            float gg = fast_tanh(p2 + d2);
            float go = 1.f / (1.f + __expf(-(p3 + d3)));
            c_state = gf * c_state + gi * gg;
            float h = go * fast_tanh(c_state);
            st_rlx(hT + (size_t)t * HID + unit,
                   ((ull)(ebase + (unsigned)t + 1u) << 32) |
                   (ull)__float_as_uint(h));
            p0 = n0; p1 = n1; p2 = n2; p3 = n3;
        }
        __syncthreads();   // protect h_sm before next step's staging overwrite
    }
}

// ---- Final linear layer ----------------------------------------------------

__global__ void k_final(const float* __restrict__ wlin,
                        const float* __restrict__ blin,
                        float* __restrict__ out)
{
    const ull* h = g_hTA + (size_t)(T_STEPS - 1) * HID;
    __shared__ float red[8];
    float s = 0.f;
    for (int j = threadIdx.x; j < HID; j += 256)
        s += __uint_as_float((unsigned)h[j]) * wlin[j];
#pragma unroll
    for (int sh = 16; sh > 0; sh >>= 1)
        s += __shfl_xor_sync(0xffffffffu, s, sh);
    if ((threadIdx.x & 31) == 0) red[threadIdx.x >> 5] = s;
    __syncthreads();
    if (threadIdx.x < 8) {
        s = red[threadIdx.x];
#pragma unroll
        for (int sh = 4; sh > 0; sh >>= 1)
            s += __shfl_xor_sync(0x000000ffu, s, sh);
        if (threadIdx.x == 0) out[0] = s + blin[0];
    }
}

// ---- launch ----------------------------------------------------------------
// Launch order puts k_rec (layer 2) at launch index 5 so the ncu capture
// (-s 5 -c 1) profiles the recurrent kernel instead of the GEMM.

extern "C" void kernel_launch(void* const* d_in, const int* in_sizes, int n_in,
                              void* d_out, int out_size)
{
    const float* seq   = (const float*)d_in[0];
    const float* w_ih0 = (const float*)d_in[1];
    const float* w_hh0 = (const float*)d_in[2];
    const float* b_ih0 = (const float*)d_in[3];
    const float* b_hh0 = (const float*)d_in[4];
    const float* w_ih1 = (const float*)d_in[5];
    const float* w_hh1 = (const float*)d_in[6];
    const float* b_ih1 = (const float*)d_in[7];
    const float* b_hh1 = (const float*)d_in[8];
    const float* w_ih2 = (const float*)d_in[9];
    const float* w_hh2 = (const float*)d_in[10];
    const float* b_ih2 = (const float*)d_in[11];
    const float* b_hh2 = (const float*)d_in[12];
    const float* w_lin = (const float*)d_in[13];
    const float* b_lin = (const float*)d_in[14];
    float* out = (float*)d_out;

    const dim3 ggrid(GATES / GR, T_STEPS / GT);

    // Layer 0: input dim 64 (plain float source)
    k_gemm<<<ggrid, 256>>>(seq, 0, 64, w_ih0, b_ih0, b_hh0);          // #0
    k_rec<<<NCTA, 256>>>(w_hh0, /*out=*/0, /*layer=*/0);              // #1
    // Layer 1: reads tagged g_hTA
    k_gemm<<<ggrid, 256>>>(nullptr, 1, HID, w_ih1, b_ih1, b_hh1);     // #2
    k_rec<<<NCTA, 256>>>(w_hh1, /*out=*/1, /*layer=*/1);              // #3
    // Layer 2: reads tagged g_hTB
    k_gemm<<<ggrid, 256>>>(nullptr, 2, HID, w_ih2, b_ih2, b_hh2);     // #4
    k_rec<<<NCTA, 256>>>(w_hh2, /*out=*/0, /*layer=*/2);              // #5 <- ncu
    // Output
    k_final<<<1, 256>>>(w_lin, b_lin, out);                           // #6
}